// round 14
// baseline (speedup 1.0000x reference)
#include <cuda_runtime.h>
#include <cuda_fp16.h>
#include <cstdint>
#include <math.h>

#define BB 512
#define TT 180
#define NM 40
#define HH 768
#define GG 3072   // 4*HH
#define PR 256
#define KC 48     // HH/16
#define NC64 12   // HH/64
#define NCTA 128  // 8 batch-tiles x 16 j-tiles

// lstm_persist dynamic smem layout (bytes)
#define SXG_OFF 98304      // stages: 3 x 32768
#define GSM_OFF 122880     // sxg: 24576
#define FS_OFF  147968     // gsm: 25088
#define LSTM_SMEM 154112   // fs: 6144

// ---- static device scratch ----
__device__ __half g_xg[(size_t)TT * BB * GG];        // [t][b][gcol] fp16
__device__ __half g_hseq0[(size_t)BB * TT * HH];
__device__ __half g_hseq1[(size_t)BB * TT * HH];
__device__ uint32_t g_hfrag[2 * 196608];             // A-frag fp16 h (ping-pong)
__device__ uint32_t g_whhf[1179648];                 // B-frag fp16 W_hh: [j0 16][kc 48][ntpair 12][lane 32][4]
__device__ uint32_t g_wihf[1179648];                 // B-frag fp16 W_ih: [n0 24][kc Kc][ntpair 8][lane 32][4]
__device__ float g_bias[GG];
__device__ unsigned g_bar;

__device__ __forceinline__ void mma16(float* d, uint4 a, uint32_t b0, uint32_t b1) {
    asm volatile(
        "mma.sync.aligned.m16n8k16.row.col.f32.f16.f16.f32 "
        "{%0,%1,%2,%3}, {%4,%5,%6,%7}, {%8,%9}, {%0,%1,%2,%3};\n"
        : "+f"(d[0]), "+f"(d[1]), "+f"(d[2]), "+f"(d[3])
        : "r"(a.x), "r"(a.y), "r"(a.z), "r"(a.w), "r"(b0), "r"(b1));
}

__device__ __forceinline__ void cp16(void* s, const void* g) {
    uint32_t sa = (uint32_t)__cvta_generic_to_shared(s);
    asm volatile("cp.async.cg.shared.global [%0], [%1], 16;\n" :: "r"(sa), "l"(g));
}
#define CPCOMMIT() asm volatile("cp.async.commit_group;\n")
#define CPW0() asm volatile("cp.async.wait_group 0;\n")
#define CPW1() asm volatile("cp.async.wait_group 1;\n")

__device__ __forceinline__ float tanh_ap(float x) {
    float y; asm("tanh.approx.f32 %0, %1;" : "=f"(y) : "f"(x)); return y;
}
__device__ __forceinline__ float sig_ap(float x) { return 0.5f * tanh_ap(0.5f * x) + 0.5f; }

__device__ __forceinline__ uint32_t packh2(float lo, float hi) {
    __half2 h = __floats2half2_rn(lo, hi);
    return *(uint32_t*)&h;
}

// ---------------------------------------------------------------------------
// prepA: both weight frag transforms in one launch (layouts unchanged).
// ---------------------------------------------------------------------------
__global__ void prepA_kernel(const float* __restrict__ Whh, __half* __restrict__ whhf,
                             const float* __restrict__ Wih, __half* __restrict__ wihf,
                             int K, int Kc) {
    int idx = blockIdx.x * 256 + threadIdx.x;
    if (idx < GG * HH) {
        int r = idx / HH, k = idx - r * HH;
        int gate = r / HH;
        int jglob = r - gate * HH;
        int j0 = jglob / 48;
        int cj = jglob - j0 * 48;
        int ncol = gate * 48 + cj;
        int kc = k >> 4, kl = k & 15;
        int ntpair = ncol >> 4, sub = (ncol >> 3) & 1, nloc = ncol & 7;
        int lane = nloc * 4 + ((kl & 7) >> 1);
        int reg = kl >> 3;
        size_t u32i = ((((size_t)j0 * KC + kc) * 12 + ntpair) * 32 + lane) * 4 + sub * 2 + reg;
        whhf[u32i * 2 + (kl & 1)] = __float2half(Whh[idx]);
    }
    int kb = Kc * 16;
    if (idx < GG * kb) {
        int r = idx / kb, k = idx - r * kb;
        int n0 = r >> 7, ncol = r & 127;
        int kc = k >> 4, kl = k & 15;
        int ntpair = ncol >> 4, sub = (ncol >> 3) & 1, nloc = ncol & 7;
        int lane = nloc * 4 + ((kl & 7) >> 1);
        int reg = kl >> 3;
        size_t u32i = ((((size_t)n0 * Kc + kc) * 8 + ntpair) * 32 + lane) * 4 + sub * 2 + reg;
        float v = (k < K) ? Wih[(size_t)r * K + k] : 0.f;
        wihf[u32i * 2 + (kl & 1)] = __float2half(v);
    }
}

// ---------------------------------------------------------------------------
__global__ void prepB_kernel(const float* __restrict__ bi, const float* __restrict__ bh,
                             float* __restrict__ bias, uint32_t* __restrict__ hf) {
    int i = blockIdx.x * 256 + threadIdx.x;
    if (i == 0) g_bar = 0u;
    if (i < GG) bias[i] = bi[i] + bh[i];
    if (i < 196608) hf[i] = 0u;
}

// ---------------------------------------------------------------------------
// Input GEMM (unchanged — known good). CTA 128m x 128n, 8 warps.
// ---------------------------------------------------------------------------
__global__ __launch_bounds__(256) void gemm_in3(
    const float* __restrict__ Af, const __half* __restrict__ Ah,
    const uint32_t* __restrict__ Bf, const float* __restrict__ bias,
    __half* __restrict__ out, int K, int Kc, int a_half)
{
    extern __shared__ __align__(16) char smd[];
    uint32_t (*As)[1024] = (uint32_t(*)[1024])smd;
    uint32_t (*Bs)[1024] = (uint32_t(*)[1024])(smd + 8192);
    __half* stg = (__half*)(smd + 16384);

    const int tid = threadIdx.x, lane = tid & 31, wid = tid >> 5;
    const int wm = wid >> 1, wn = wid & 1;
    const int n0 = blockIdx.x, m0 = blockIdx.y;
    const int g = lane >> 2, tg = lane & 3;

    float acc[2][8][4];
    #pragma unroll
    for (int i = 0; i < 2; i++)
        #pragma unroll
        for (int j = 0; j < 8; j++)
            #pragma unroll
            for (int k = 0; k < 4; k++) acc[i][j][k] = 0.f;

    const int row = tid >> 1, kp = (tid & 1) * 8;
    const int mt = row >> 4, mloc = row & 15;
    const int regbase = (kp >> 3) * 2 + (mloc >> 3);
    const uint32_t* Bbase = Bf + (size_t)n0 * Kc * 1024;

    uint32_t av[4];
    auto ldgA = [&](int kc) {
        int k0 = kc * 16;
        if (a_half) {
            const __half* src = Ah + (size_t)(m0 * 128 + row) * K + k0 + kp;
            uint4 v = *(const uint4*)src;
            av[0] = v.x; av[1] = v.y; av[2] = v.z; av[3] = v.w;
        } else {
            float t0[4] = {0, 0, 0, 0}, t1[4] = {0, 0, 0, 0};
            const float* src = Af + (size_t)(m0 * 128 + row) * K + k0 + kp;
            if (k0 + kp < K)     *(float4*)t0 = *(const float4*)src;
            if (k0 + kp + 4 < K) *(float4*)t1 = *(const float4*)(src + 4);
            av[0] = packh2(t0[0], t0[1]); av[1] = packh2(t0[2], t0[3]);
            av[2] = packh2(t1[0], t1[1]); av[3] = packh2(t1[2], t1[3]);
        }
    };
    auto stsA = [&](int buf) {
        #pragma unroll
        for (int i = 0; i < 4; i++)
            As[buf][(mt * 32 + (mloc & 7) * 4 + i) * 4 + regbase] = av[i];
    };
    auto cpB = [&](int buf, int kc) {
        const uint32_t* src = Bbase + (size_t)kc * 1024;
        cp16(&Bs[buf][tid * 4], src + tid * 4);
    };

    ldgA(0); cpB(0, 0); CPCOMMIT();
    stsA(0);
    CPW0();
    __syncthreads();

    for (int kc = 0; kc < Kc; kc++) {
        int cur = kc & 1, nxt = cur ^ 1;
        if (kc + 1 < Kc) { cpB(nxt, kc + 1); CPCOMMIT(); ldgA(kc + 1); }
        uint4 af[2];
        #pragma unroll
        for (int mti = 0; mti < 2; mti++)
            af[mti] = *(const uint4*)&As[cur][((2 * wm + mti) * 32 + lane) * 4];
        #pragma unroll
        for (int p = 0; p < 4; p++) {
            uint4 bq = *(const uint4*)&Bs[cur][((wn * 4 + p) * 32 + lane) * 4];
            mma16(acc[0][2 * p], af[0], bq.x, bq.y);
            mma16(acc[1][2 * p], af[1], bq.x, bq.y);
            mma16(acc[0][2 * p + 1], af[0], bq.z, bq.w);
            mma16(acc[1][2 * p + 1], af[1], bq.z, bq.w);
        }
        if (kc + 1 < Kc) { stsA(nxt); CPW0(); }
        __syncthreads();
    }

    #pragma unroll
    for (int mti = 0; mti < 2; mti++)
        #pragma unroll
        for (int nt = 0; nt < 8; nt++)
            #pragma unroll
            for (int rh = 0; rh < 2; rh++) {
                int rrow = wm * 32 + mti * 16 + g + rh * 8;
                int coll = wn * 64 + nt * 8 + 2 * tg;
                float v0 = acc[mti][nt][rh * 2 + 0] + __ldg(&bias[n0 * 128 + coll]);
                float v1 = acc[mti][nt][rh * 2 + 1] + __ldg(&bias[n0 * 128 + coll + 1]);
                *(__half2*)&stg[rrow * 128 + coll] = __floats2half2_rn(v0, v1);
            }
    __syncthreads();
    #pragma unroll
    for (int i = 0; i < 8; i++) {
        int unit = tid + i * 256;
        int rrow = unit >> 4, u = unit & 15;
        int m = m0 * 128 + rrow;
        int b = m / TT, t = m - b * TT;
        __half* dst = &out[((size_t)t * BB + b) * GG + n0 * 128];
        *(uint4*)((char*)dst + u * 16) = *(const uint4*)((char*)&stg[rrow * 128] + u * 16);
    }
}

// ---------------------------------------------------------------------------
// Persistent LSTM layer — 512 threads (16 warps) per CTA for latency hiding.
// 128 CTAs (8m x 16j). Warps: wm(2) x wn(8); warp tile 32m x 3 n8-tiles
// {wn, wn+8, wn+16}. K-chunk 64, 3 stages, pre-barrier W/xg prefetch.
// ---------------------------------------------------------------------------
__global__ __launch_bounds__(512, 1) void lstm_persist(
    const uint32_t* __restrict__ Wf, const __half* __restrict__ xg,
    uint32_t* __restrict__ hfA, uint32_t* __restrict__ hfB,
    __half* __restrict__ hseq, int seq_all)
{
    extern __shared__ __align__(16) char smc[];
    __half* sxg = (__half*)(smc + SXG_OFF);     // [bl 64][gate 4][cj 48]
    float* gsm = (float*)(smc + GSM_OFF);
    __half* fsh = (__half*)(smc + FS_OFF);
    uint32_t* fsu = (uint32_t*)fsh;

    const int tid = threadIdx.x, lane = tid & 31, wid = tid >> 5;
    const int wm = wid >> 3, wn = wid & 7;
    const int m0 = blockIdx.x & 7, j0 = blockIdx.x >> 3;   // j0: 0..15
    const int g = lane >> 2, tg = lane & 3;
    const uint32_t* Bb = Wf + (size_t)j0 * (KC * 1536);

    float creg[2][4];
    #pragma unroll
    for (int p = 0; p < 2; p++)
        #pragma unroll
        for (int i = 0; i < 4; i++) creg[p][i] = 0.f;

    const int ecj = tid % 48;
    const int er0 = tid / 48;     // 0..7 valid when tid < 384

    // B-part of a chunk64 stage (t-independent)
    auto cpB = [&](int kcc) {
        uint32_t* dst = (uint32_t*)(smc + (kcc % 3) * 32768);
        const uint32_t* b = Bb + (size_t)kcc * 6144;
        #pragma unroll
        for (int i = 0; i < 3; i++)
            cp16(&dst[2048 + (tid + i * 512) * 4], b + (tid + i * 512) * 4);
    };
    // xg tile prefetch for step tt
    auto cpXG = [&](int tt) {
        #pragma unroll
        for (int i = 0; i < 3; i++) {
            int u = tid + i * 512;
            int bl = u / 24, rem = u - bl * 24;
            int gate = rem / 6, s = rem - gate * 6;
            const __half* src = xg + ((size_t)tt * BB + m0 * 64 + bl) * GG +
                                gate * HH + j0 * 48 + s * 8;
            cp16(&sxg[(bl * 4 + gate) * 48 + s * 8], src);
        }
    };

    // initial P group for t = 0
    cpB(0); cpB(1); cpXG(0); CPCOMMIT();

    for (int t = 0; t < TT; t++) {
        const uint32_t* Ain = ((t & 1) ? hfB : hfA) + (size_t)m0 * (KC * 512);
        uint32_t* Hout = (t & 1) ? hfA : hfB;

        auto cpA = [&](int kcc) {
            uint32_t* dst = (uint32_t*)(smc + (kcc % 3) * 32768);
            const uint32_t* a = Ain + (size_t)kcc * 2048;
            cp16(&dst[tid * 4], a + tid * 4);
        };

        float acc[2][3][4];
        #pragma unroll
        for (int i = 0; i < 2; i++)
            #pragma unroll
            for (int j = 0; j < 3; j++)
                #pragma unroll
                for (int k = 0; k < 4; k++) acc[i][j][k] = 0.f;

        // post-barrier: only A loads are cold
        cpA(0); CPCOMMIT();
        cpA(1); CPCOMMIT();

        for (int kcc = 0; kcc < NC64; kcc++) {
            if (kcc < NC64 - 1) CPW1(); else CPW0();
            __syncthreads();
            if (kcc + 2 < NC64) { cpA(kcc + 2); cpB(kcc + 2); CPCOMMIT(); }
            const uint32_t* stgb = (const uint32_t*)(smc + (kcc % 3) * 32768);
            #pragma unroll
            for (int q = 0; q < 4; q++) {
                const uint32_t* sA = stgb + q * 512;
                const uint32_t* sB = stgb + 2048 + q * 1536;
                uint4 af[2];
                #pragma unroll
                for (int mti = 0; mti < 2; mti++)
                    af[mti] = *(const uint4*)&sA[((2 * wm + mti) * 32 + lane) * 4];
                #pragma unroll
                for (int p = 0; p < 3; p++) {
                    int t8 = wn + 8 * p;
                    uint2 bb = *(const uint2*)&sB[((t8 >> 1) * 32 + lane) * 4 + (t8 & 1) * 2];
                    mma16(acc[0][p], af[0], bb.x, bb.y);
                    mma16(acc[1][p], af[1], bb.x, bb.y);
                }
            }
        }

        // ---- epilogue: two 32-row passes through smem gate transpose ----
        for (int p = 0; p < 2; p++) {
            __syncthreads();
            if (wm == p) {
                #pragma unroll
                for (int mti = 0; mti < 2; mti++)
                    #pragma unroll
                    for (int pp = 0; pp < 3; pp++)
                        #pragma unroll
                        for (int r2 = 0; r2 < 4; r2++) {
                            int mi = mti * 16 + g + ((r2 & 2) ? 8 : 0);
                            int ncol = (wn + 8 * pp) * 8 + 2 * tg + (r2 & 1);
                            gsm[mi * 196 + ncol + ncol / 48] = acc[mti][pp][r2];
                        }
            }
            __syncthreads();
            if (tid < 384) {
                #pragma unroll
                for (int i = 0; i < 4; i++) {
                    int r = er0 + 8 * i;
                    int bl = p * 32 + r;
                    int b = m0 * 64 + bl;
                    int j = j0 * 48 + ecj;
                    const __half* xh = &sxg[bl * 192 + ecj];
                    float pi = gsm[r * 196 + 0 * 49 + ecj] + __half2float(xh[0]);
                    float pf = gsm[r * 196 + 1 * 49 + ecj] + __half2float(xh[48]);
                    float pg = gsm[r * 196 + 2 * 49 + ecj] + __half2float(xh[96]);
                    float po = gsm[r * 196 + 3 * 49 + ecj] + __half2float(xh[144]);
                    float iv = sig_ap(pi), fv = sig_ap(pf), gv = tanh_ap(pg), ov = sig_ap(po);
                    float cn = fv * creg[p][i] + iv * gv;
                    creg[p][i] = cn;
                    float hn = ov * tanh_ap(cn);
                    if (seq_all || t == TT - 1)
                        hseq[((size_t)b * TT + t) * HH + j] = __float2half(hn);
                    int q = ecj >> 4, kl = ecj & 15;
                    int mt = bl >> 4, mloc = bl & 15;
                    int lf = (mloc & 7) * 4 + ((kl & 7) >> 1);
                    int reg = (kl >> 3) * 2 + (mloc >> 3);
                    fsh[((((q * 4 + mt) * 32 + lf) * 4) + reg) * 2 + (kl & 1)] =
                        __float2half(hn);
                }
            }
        }
        __syncthreads();
        if (t < TT - 1) {
            // coalesced frag store (1536 u32 = 384 uint4)
            size_t fb = ((size_t)m0 * KC + (size_t)j0 * 3) * 512;
            if (tid < 384)
                *(uint4*)&Hout[fb + tid * 4] = *(const uint4*)&fsu[tid * 4];
            // prefetch next step's W chunks 0,1 + xg while waiting on the barrier
            cpB(0); cpB(1); cpXG(t + 1); CPCOMMIT();
            __threadfence();
            __syncthreads();
            if (tid == 0) {
                atomicAdd(&g_bar, 1u);
                unsigned target = (unsigned)NCTA * (unsigned)(t + 1);
                while (true) {
                    unsigned v;
                    asm volatile("ld.global.acquire.gpu.u32 %0, [%1];"
                                 : "=r"(v) : "l"(&g_bar));
                    if (v >= target) break;
                    __nanosleep(16);
                }
            }
            __syncthreads();
        }
    }
}

// ---------------------------------------------------------------------------
// Projection + L2 normalize from hseq[:, T-1, :]
// ---------------------------------------------------------------------------
__global__ __launch_bounds__(256) void proj_kernel(
    const __half* __restrict__ hseq, const float* __restrict__ pw,
    const float* __restrict__ pb, float* __restrict__ out)
{
    __shared__ float hs[8][HH];
    __shared__ float red[256];
    const int b0 = blockIdx.x * 8;
    const int tid = threadIdx.x;

    for (int i = tid; i < 8 * HH; i += 256) {
        int r = i / HH, k = i % HH;
        hs[r][k] = __half2float(hseq[((size_t)(b0 + r) * TT + (TT - 1)) * HH + k]);
    }
    __syncthreads();

    float s[8];
    float bias = pb[tid];
    #pragma unroll
    for (int r = 0; r < 8; r++) s[r] = bias;
    const float* w = pw + (size_t)tid * HH;
    for (int k = 0; k < HH; k++) {
        float wv = w[k];
        #pragma unroll
        for (int r = 0; r < 8; r++) s[r] += wv * hs[r][k];
    }

    for (int r = 0; r < 8; r++) {
        red[tid] = s[r] * s[r];
        __syncthreads();
        for (int off = 128; off > 0; off >>= 1) {
            if (tid < off) red[tid] += red[tid + off];
            __syncthreads();
        }
        float rn = rsqrtf(red[0]);
        __syncthreads();
        out[(size_t)(b0 + r) * PR + tid] = s[r] * rn;
    }
}

// ---------------------------------------------------------------------------
// host
// ---------------------------------------------------------------------------
extern "C" void kernel_launch(void* const* d_in, const int* in_sizes, int n_in,
                              void* d_out, int out_size)
{
    const float* x = (const float*)d_in[0];
    const float* w_ih[3] = {(const float*)d_in[1], (const float*)d_in[5], (const float*)d_in[9]};
    const float* w_hh[3] = {(const float*)d_in[2], (const float*)d_in[6], (const float*)d_in[10]};
    const float* b_ih[3] = {(const float*)d_in[3], (const float*)d_in[7], (const float*)d_in[11]};
    const float* b_hh[3] = {(const float*)d_in[4], (const float*)d_in[8], (const float*)d_in[12]};
    const float* pw = (const float*)d_in[13];
    const float* pb = (const float*)d_in[14];
    float* out = (float*)d_out;

    cudaFuncSetAttribute(lstm_persist, cudaFuncAttributeMaxDynamicSharedMemorySize, LSTM_SMEM);
    cudaFuncSetAttribute(gemm_in3, cudaFuncAttributeMaxDynamicSharedMemorySize, 49152);

    __half *xg_p, *hs0_p, *hs1_p;
    uint32_t *hf_p, *whhf_p, *wihf_p;
    float *bias_p;
    cudaGetSymbolAddress((void**)&xg_p, g_xg);
    cudaGetSymbolAddress((void**)&hs0_p, g_hseq0);
    cudaGetSymbolAddress((void**)&hs1_p, g_hseq1);
    cudaGetSymbolAddress((void**)&hf_p, g_hfrag);
    cudaGetSymbolAddress((void**)&whhf_p, g_whhf);
    cudaGetSymbolAddress((void**)&wihf_p, g_wihf);
    cudaGetSymbolAddress((void**)&bias_p, g_bias);
    uint32_t* hf0 = hf_p;
    uint32_t* hf1 = hf_p + 196608;

    const __half* inH[3] = {nullptr, hs0_p, hs1_p};
    __half* outH[3] = {hs0_p, hs1_p, hs0_p};
    int Ks[3] = {NM, HH, HH};
    int Kcs[3] = {3, KC, KC};

    for (int l = 0; l < 3; l++) {
        prepA_kernel<<<(GG * HH + 255) / 256, 256>>>(w_hh[l], (__half*)whhf_p,
                                                     w_ih[l], (__half*)wihf_p,
                                                     Ks[l], Kcs[l]);
        prepB_kernel<<<768, 256>>>(b_ih[l], b_hh[l], bias_p, hf0);
        gemm_in3<<<dim3(GG / 128, (BB * TT) / 128), 256, 49152>>>(
            (l == 0) ? x : nullptr, inH[l], wihf_p, bias_p, xg_p, Ks[l], Kcs[l],
            (l == 0) ? 0 : 1);
        lstm_persist<<<NCTA, 512, LSTM_SMEM>>>(whhf_p, xg_p, hf0, hf1, outH[l],
                                               (l < 2) ? 1 : 0);
    }
    proj_kernel<<<BB / 8, 256>>>(hs0_p, pw, pb, out);
}

// round 15
// speedup vs baseline: 1.7929x; 1.7929x over previous
#include <cuda_runtime.h>
#include <cuda_fp16.h>
#include <cstdint>
#include <math.h>

#define BB 512
#define TT 180
#define NM 40
#define HH 768
#define GG 3072   // 4*HH
#define PR 256
#define KC 48     // HH/16
#define NC64 12   // HH/64
#define NCTA 128  // 8 batch-tiles x 16 j-tiles

// lstm_persist dynamic smem layout (bytes)
#define SXG_OFF 98304      // stages: 3 x 32768
#define GSM_OFF 122880     // sxg: 24576
#define FS_OFF  173056     // gsm: 50176 (64 rows x 196 floats)
#define LSTM_SMEM 179200   // fs: 6144

// ---- static device scratch ----
__device__ __half g_xg[(size_t)TT * BB * GG];        // [t][b][gcol] fp16
__device__ __half g_hseq0[(size_t)BB * TT * HH];
__device__ __half g_hseq1[(size_t)BB * TT * HH];
__device__ uint32_t g_hfrag[2 * 196608];             // A-frag fp16 h (ping-pong)
__device__ uint32_t g_whhf[1179648];                 // B-frag fp16 W_hh: [j0 16][kc 48][ntpair 12][lane 32][4]
__device__ uint32_t g_wihf[1179648];                 // B-frag fp16 W_ih: [n0 24][kc Kc][ntpair 8][lane 32][4]
__device__ float g_bias[GG];
__device__ unsigned g_bar;

__device__ __forceinline__ void mma16(float* d, uint4 a, uint32_t b0, uint32_t b1) {
    asm volatile(
        "mma.sync.aligned.m16n8k16.row.col.f32.f16.f16.f32 "
        "{%0,%1,%2,%3}, {%4,%5,%6,%7}, {%8,%9}, {%0,%1,%2,%3};\n"
        : "+f"(d[0]), "+f"(d[1]), "+f"(d[2]), "+f"(d[3])
        : "r"(a.x), "r"(a.y), "r"(a.z), "r"(a.w), "r"(b0), "r"(b1));
}

__device__ __forceinline__ void cp16(void* s, const void* g) {
    uint32_t sa = (uint32_t)__cvta_generic_to_shared(s);
    asm volatile("cp.async.cg.shared.global [%0], [%1], 16;\n" :: "r"(sa), "l"(g));
}
#define CPCOMMIT() asm volatile("cp.async.commit_group;\n")
#define CPW0() asm volatile("cp.async.wait_group 0;\n")
#define CPW1() asm volatile("cp.async.wait_group 1;\n")

__device__ __forceinline__ float tanh_ap(float x) {
    float y; asm("tanh.approx.f32 %0, %1;" : "=f"(y) : "f"(x)); return y;
}
__device__ __forceinline__ float sig_ap(float x) { return 0.5f * tanh_ap(0.5f * x) + 0.5f; }

__device__ __forceinline__ uint32_t packh2(float lo, float hi) {
    __half2 h = __floats2half2_rn(lo, hi);
    return *(uint32_t*)&h;
}

// ---------------------------------------------------------------------------
// prepA: both weight frag transforms in one launch (layouts unchanged).
// ---------------------------------------------------------------------------
__global__ void prepA_kernel(const float* __restrict__ Whh, __half* __restrict__ whhf,
                             const float* __restrict__ Wih, __half* __restrict__ wihf,
                             int K, int Kc) {
    int idx = blockIdx.x * 256 + threadIdx.x;
    if (idx < GG * HH) {
        int r = idx / HH, k = idx - r * HH;
        int gate = r / HH;
        int jglob = r - gate * HH;
        int j0 = jglob / 48;
        int cj = jglob - j0 * 48;
        int ncol = gate * 48 + cj;
        int kc = k >> 4, kl = k & 15;
        int ntpair = ncol >> 4, sub = (ncol >> 3) & 1, nloc = ncol & 7;
        int lane = nloc * 4 + ((kl & 7) >> 1);
        int reg = kl >> 3;
        size_t u32i = ((((size_t)j0 * KC + kc) * 12 + ntpair) * 32 + lane) * 4 + sub * 2 + reg;
        whhf[u32i * 2 + (kl & 1)] = __float2half(Whh[idx]);
    }
    int kb = Kc * 16;
    if (idx < GG * kb) {
        int r = idx / kb, k = idx - r * kb;
        int n0 = r >> 7, ncol = r & 127;
        int kc = k >> 4, kl = k & 15;
        int ntpair = ncol >> 4, sub = (ncol >> 3) & 1, nloc = ncol & 7;
        int lane = nloc * 4 + ((kl & 7) >> 1);
        int reg = kl >> 3;
        size_t u32i = ((((size_t)n0 * Kc + kc) * 8 + ntpair) * 32 + lane) * 4 + sub * 2 + reg;
        float v = (k < K) ? Wih[(size_t)r * K + k] : 0.f;
        wihf[u32i * 2 + (kl & 1)] = __float2half(v);
    }
}

// ---------------------------------------------------------------------------
__global__ void prepB_kernel(const float* __restrict__ bi, const float* __restrict__ bh,
                             float* __restrict__ bias, uint32_t* __restrict__ hf) {
    int i = blockIdx.x * 256 + threadIdx.x;
    if (i == 0) g_bar = 0u;
    if (i < GG) bias[i] = bi[i] + bh[i];
    if (i < 196608) hf[i] = 0u;
}

// ---------------------------------------------------------------------------
// Input GEMM (unchanged — known good). CTA 128m x 128n, 8 warps.
// ---------------------------------------------------------------------------
__global__ __launch_bounds__(256) void gemm_in3(
    const float* __restrict__ Af, const __half* __restrict__ Ah,
    const uint32_t* __restrict__ Bf, const float* __restrict__ bias,
    __half* __restrict__ out, int K, int Kc, int a_half)
{
    extern __shared__ __align__(16) char smd[];
    uint32_t (*As)[1024] = (uint32_t(*)[1024])smd;
    uint32_t (*Bs)[1024] = (uint32_t(*)[1024])(smd + 8192);
    __half* stg = (__half*)(smd + 16384);

    const int tid = threadIdx.x, lane = tid & 31, wid = tid >> 5;
    const int wm = wid >> 1, wn = wid & 1;
    const int n0 = blockIdx.x, m0 = blockIdx.y;
    const int g = lane >> 2, tg = lane & 3;

    float acc[2][8][4];
    #pragma unroll
    for (int i = 0; i < 2; i++)
        #pragma unroll
        for (int j = 0; j < 8; j++)
            #pragma unroll
            for (int k = 0; k < 4; k++) acc[i][j][k] = 0.f;

    const int row = tid >> 1, kp = (tid & 1) * 8;
    const int mt = row >> 4, mloc = row & 15;
    const int regbase = (kp >> 3) * 2 + (mloc >> 3);
    const uint32_t* Bbase = Bf + (size_t)n0 * Kc * 1024;

    uint32_t av[4];
    auto ldgA = [&](int kc) {
        int k0 = kc * 16;
        if (a_half) {
            const __half* src = Ah + (size_t)(m0 * 128 + row) * K + k0 + kp;
            uint4 v = *(const uint4*)src;
            av[0] = v.x; av[1] = v.y; av[2] = v.z; av[3] = v.w;
        } else {
            float t0[4] = {0, 0, 0, 0}, t1[4] = {0, 0, 0, 0};
            const float* src = Af + (size_t)(m0 * 128 + row) * K + k0 + kp;
            if (k0 + kp < K)     *(float4*)t0 = *(const float4*)src;
            if (k0 + kp + 4 < K) *(float4*)t1 = *(const float4*)(src + 4);
            av[0] = packh2(t0[0], t0[1]); av[1] = packh2(t0[2], t0[3]);
            av[2] = packh2(t1[0], t1[1]); av[3] = packh2(t1[2], t1[3]);
        }
    };
    auto stsA = [&](int buf) {
        #pragma unroll
        for (int i = 0; i < 4; i++)
            As[buf][(mt * 32 + (mloc & 7) * 4 + i) * 4 + regbase] = av[i];
    };
    auto cpB = [&](int buf, int kc) {
        const uint32_t* src = Bbase + (size_t)kc * 1024;
        cp16(&Bs[buf][tid * 4], src + tid * 4);
    };

    ldgA(0); cpB(0, 0); CPCOMMIT();
    stsA(0);
    CPW0();
    __syncthreads();

    for (int kc = 0; kc < Kc; kc++) {
        int cur = kc & 1, nxt = cur ^ 1;
        if (kc + 1 < Kc) { cpB(nxt, kc + 1); CPCOMMIT(); ldgA(kc + 1); }
        uint4 af[2];
        #pragma unroll
        for (int mti = 0; mti < 2; mti++)
            af[mti] = *(const uint4*)&As[cur][((2 * wm + mti) * 32 + lane) * 4];
        #pragma unroll
        for (int p = 0; p < 4; p++) {
            uint4 bq = *(const uint4*)&Bs[cur][((wn * 4 + p) * 32 + lane) * 4];
            mma16(acc[0][2 * p], af[0], bq.x, bq.y);
            mma16(acc[1][2 * p], af[1], bq.x, bq.y);
            mma16(acc[0][2 * p + 1], af[0], bq.z, bq.w);
            mma16(acc[1][2 * p + 1], af[1], bq.z, bq.w);
        }
        if (kc + 1 < Kc) { stsA(nxt); CPW0(); }
        __syncthreads();
    }

    #pragma unroll
    for (int mti = 0; mti < 2; mti++)
        #pragma unroll
        for (int nt = 0; nt < 8; nt++)
            #pragma unroll
            for (int rh = 0; rh < 2; rh++) {
                int rrow = wm * 32 + mti * 16 + g + rh * 8;
                int coll = wn * 64 + nt * 8 + 2 * tg;
                float v0 = acc[mti][nt][rh * 2 + 0] + __ldg(&bias[n0 * 128 + coll]);
                float v1 = acc[mti][nt][rh * 2 + 1] + __ldg(&bias[n0 * 128 + coll + 1]);
                *(__half2*)&stg[rrow * 128 + coll] = __floats2half2_rn(v0, v1);
            }
    __syncthreads();
    #pragma unroll
    for (int i = 0; i < 8; i++) {
        int unit = tid + i * 256;
        int rrow = unit >> 4, u = unit & 15;
        int m = m0 * 128 + rrow;
        int b = m / TT, t = m - b * TT;
        __half* dst = &out[((size_t)t * BB + b) * GG + n0 * 128];
        *(uint4*)((char*)dst + u * 16) = *(const uint4*)((char*)&stg[rrow * 128] + u * 16);
    }
}

// ---------------------------------------------------------------------------
// Persistent LSTM layer — round-13 structure (256 thr, LDS.128 everywhere),
// with a SINGLE-PASS epilogue: all 8 warps write the 64-row gate transpose
// concurrently (disjoint rows via wm), one sync, one consumer sweep.
// ---------------------------------------------------------------------------
__global__ __launch_bounds__(256, 1) void lstm_persist(
    const uint32_t* __restrict__ Wf, const __half* __restrict__ xg,
    uint32_t* __restrict__ hfA, uint32_t* __restrict__ hfB,
    __half* __restrict__ hseq, int seq_all)
{
    extern __shared__ __align__(16) char smc[];
    __half* sxg = (__half*)(smc + SXG_OFF);     // [bl 64][gate 4][cj 48]
    float* gsm = (float*)(smc + GSM_OFF);       // [mi 64][gate 4][49]
    __half* fsh = (__half*)(smc + FS_OFF);
    uint32_t* fsu = (uint32_t*)fsh;

    const int tid = threadIdx.x, lane = tid & 31, wid = tid >> 5;
    const int wm = wid >> 2, wn = wid & 3;
    const int m0 = blockIdx.x & 7, j0 = blockIdx.x >> 3;   // j0: 0..15
    const int g = lane >> 2, tg = lane & 3;
    const uint32_t* Bb = Wf + (size_t)j0 * (KC * 1536);

    float creg[16];
    #pragma unroll
    for (int i = 0; i < 16; i++) creg[i] = 0.f;

    const int ecj = tid % 48;
    const int er0 = tid / 48;     // 0..3 valid when tid < 192

    // B-part of a chunk64 stage (t-independent)
    auto cpB = [&](int kcc) {
        uint32_t* dst = (uint32_t*)(smc + (kcc % 3) * 32768);
        const uint32_t* b = Bb + (size_t)kcc * 6144;
        #pragma unroll
        for (int i = 0; i < 6; i++)
            cp16(&dst[2048 + (tid + i * 256) * 4], b + (tid + i * 256) * 4);
    };
    // xg tile prefetch for step tt
    auto cpXG = [&](int tt) {
        #pragma unroll
        for (int i = 0; i < 6; i++) {
            int u = tid + i * 256;
            int bl = u / 24, rem = u - bl * 24;
            int gate = rem / 6, s = rem - gate * 6;
            const __half* src = xg + ((size_t)tt * BB + m0 * 64 + bl) * GG +
                                gate * HH + j0 * 48 + s * 8;
            cp16(&sxg[(bl * 4 + gate) * 48 + s * 8], src);
        }
    };

    // initial P group for t = 0
    cpB(0); cpB(1); cpXG(0); CPCOMMIT();

    for (int t = 0; t < TT; t++) {
        const uint32_t* Ain = ((t & 1) ? hfB : hfA) + (size_t)m0 * (KC * 512);
        uint32_t* Hout = (t & 1) ? hfA : hfB;

        auto cpA = [&](int kcc) {
            uint32_t* dst = (uint32_t*)(smc + (kcc % 3) * 32768);
            const uint32_t* a = Ain + (size_t)kcc * 2048;
            cp16(&dst[tid * 4], a + tid * 4);
            cp16(&dst[(tid + 256) * 4], a + (tid + 256) * 4);
        };

        float acc[2][6][4];
        #pragma unroll
        for (int i = 0; i < 2; i++)
            #pragma unroll
            for (int j = 0; j < 6; j++)
                #pragma unroll
                for (int k = 0; k < 4; k++) acc[i][j][k] = 0.f;

        // post-barrier: only A loads are cold
        cpA(0); CPCOMMIT();
        cpA(1); CPCOMMIT();

        for (int kcc = 0; kcc < NC64; kcc++) {
            if (kcc < NC64 - 1) CPW1(); else CPW0();
            __syncthreads();
            if (kcc + 2 < NC64) { cpA(kcc + 2); cpB(kcc + 2); CPCOMMIT(); }
            const uint32_t* stgb = (const uint32_t*)(smc + (kcc % 3) * 32768);
            #pragma unroll
            for (int q = 0; q < 4; q++) {
                const uint32_t* sA = stgb + q * 512;
                const uint32_t* sB = stgb + 2048 + q * 1536;
                uint4 af[2];
                #pragma unroll
                for (int mti = 0; mti < 2; mti++)
                    af[mti] = *(const uint4*)&sA[((2 * wm + mti) * 32 + lane) * 4];
                #pragma unroll
                for (int p = 0; p < 3; p++) {
                    uint4 bq = *(const uint4*)&sB[((wn * 3 + p) * 32 + lane) * 4];
                    mma16(acc[0][2 * p], af[0], bq.x, bq.y);
                    mma16(acc[1][2 * p], af[1], bq.x, bq.y);
                    mma16(acc[0][2 * p + 1], af[0], bq.z, bq.w);
                    mma16(acc[1][2 * p + 1], af[1], bq.z, bq.w);
                }
            }
        }

        // ---- unified single-pass epilogue ----
        #pragma unroll
        for (int mti = 0; mti < 2; mti++)
            #pragma unroll
            for (int nt = 0; nt < 6; nt++)
                #pragma unroll
                for (int r2 = 0; r2 < 4; r2++) {
                    int mi = wm * 32 + mti * 16 + g + ((r2 & 2) ? 8 : 0);
                    int cj = nt * 8 + 2 * tg + (r2 & 1);
                    gsm[mi * 196 + wn * 49 + cj] = acc[mti][nt][r2];
                }
        __syncthreads();
        if (tid < 192) {
            #pragma unroll
            for (int i = 0; i < 16; i++) {
                int bl = er0 + 4 * i;          // 0..63
                int b = m0 * 64 + bl;
                int j = j0 * 48 + ecj;
                const __half* xh = &sxg[bl * 192 + ecj];
                float pi = gsm[bl * 196 + 0 * 49 + ecj] + __half2float(xh[0]);
                float pf = gsm[bl * 196 + 1 * 49 + ecj] + __half2float(xh[48]);
                float pg = gsm[bl * 196 + 2 * 49 + ecj] + __half2float(xh[96]);
                float po = gsm[bl * 196 + 3 * 49 + ecj] + __half2float(xh[144]);
                float iv = sig_ap(pi), fv = sig_ap(pf), gv = tanh_ap(pg), ov = sig_ap(po);
                float cn = fv * creg[i] + iv * gv;
                creg[i] = cn;
                float hn = ov * tanh_ap(cn);
                if (seq_all || t == TT - 1)
                    hseq[((size_t)b * TT + t) * HH + j] = __float2half(hn);
                int q = ecj >> 4, kl = ecj & 15;
                int mt = bl >> 4, mloc = bl & 15;
                int lf = (mloc & 7) * 4 + ((kl & 7) >> 1);
                int reg = (kl >> 3) * 2 + (mloc >> 3);
                fsh[((((q * 4 + mt) * 32 + lf) * 4) + reg) * 2 + (kl & 1)] =
                    __float2half(hn);
            }
        }
        __syncthreads();
        if (t < TT - 1) {
            // coalesced frag store (1536 u32 = 384 uint4)
            size_t fb = ((size_t)m0 * KC + (size_t)j0 * 3) * 512;
            #pragma unroll
            for (int i = 0; i < 2; i++) {
                int e = tid + i * 256;
                if (e < 384)
                    *(uint4*)&Hout[fb + e * 4] = *(const uint4*)&fsu[e * 4];
            }
            // prefetch next step's W chunks 0,1 + xg while waiting on the barrier
            cpB(0); cpB(1); cpXG(t + 1); CPCOMMIT();
            __threadfence();
            __syncthreads();
            if (tid == 0) {
                atomicAdd(&g_bar, 1u);
                unsigned target = (unsigned)NCTA * (unsigned)(t + 1);
                while (true) {
                    unsigned v;
                    asm volatile("ld.global.acquire.gpu.u32 %0, [%1];"
                                 : "=r"(v) : "l"(&g_bar));
                    if (v >= target) break;
                    __nanosleep(16);
                }
            }
            __syncthreads();
        }
    }
}

// ---------------------------------------------------------------------------
// Projection + L2 normalize from hseq[:, T-1, :]
// ---------------------------------------------------------------------------
__global__ __launch_bounds__(256) void proj_kernel(
    const __half* __restrict__ hseq, const float* __restrict__ pw,
    const float* __restrict__ pb, float* __restrict__ out)
{
    __shared__ float hs[8][HH];
    __shared__ float red[256];
    const int b0 = blockIdx.x * 8;
    const int tid = threadIdx.x;

    for (int i = tid; i < 8 * HH; i += 256) {
        int r = i / HH, k = i % HH;
        hs[r][k] = __half2float(hseq[((size_t)(b0 + r) * TT + (TT - 1)) * HH + k]);
    }
    __syncthreads();

    float s[8];
    float bias = pb[tid];
    #pragma unroll
    for (int r = 0; r < 8; r++) s[r] = bias;
    const float* w = pw + (size_t)tid * HH;
    for (int k = 0; k < HH; k++) {
        float wv = w[k];
        #pragma unroll
        for (int r = 0; r < 8; r++) s[r] += wv * hs[r][k];
    }

    for (int r = 0; r < 8; r++) {
        red[tid] = s[r] * s[r];
        __syncthreads();
        for (int off = 128; off > 0; off >>= 1) {
            if (tid < off) red[tid] += red[tid + off];
            __syncthreads();
        }
        float rn = rsqrtf(red[0]);
        __syncthreads();
        out[(size_t)(b0 + r) * PR + tid] = s[r] * rn;
    }
}

// ---------------------------------------------------------------------------
// host
// ---------------------------------------------------------------------------
extern "C" void kernel_launch(void* const* d_in, const int* in_sizes, int n_in,
                              void* d_out, int out_size)
{
    const float* x = (const float*)d_in[0];
    const float* w_ih[3] = {(const float*)d_in[1], (const float*)d_in[5], (const float*)d_in[9]};
    const float* w_hh[3] = {(const float*)d_in[2], (const float*)d_in[6], (const float*)d_in[10]};
    const float* b_ih[3] = {(const float*)d_in[3], (const float*)d_in[7], (const float*)d_in[11]};
    const float* b_hh[3] = {(const float*)d_in[4], (const float*)d_in[8], (const float*)d_in[12]};
    const float* pw = (const float*)d_in[13];
    const float* pb = (const float*)d_in[14];
    float* out = (float*)d_out;

    cudaFuncSetAttribute(lstm_persist, cudaFuncAttributeMaxDynamicSharedMemorySize, LSTM_SMEM);
    cudaFuncSetAttribute(gemm_in3, cudaFuncAttributeMaxDynamicSharedMemorySize, 49152);

    __half *xg_p, *hs0_p, *hs1_p;
    uint32_t *hf_p, *whhf_p, *wihf_p;
    float *bias_p;
    cudaGetSymbolAddress((void**)&xg_p, g_xg);
    cudaGetSymbolAddress((void**)&hs0_p, g_hseq0);
    cudaGetSymbolAddress((void**)&hs1_p, g_hseq1);
    cudaGetSymbolAddress((void**)&hf_p, g_hfrag);
    cudaGetSymbolAddress((void**)&whhf_p, g_whhf);
    cudaGetSymbolAddress((void**)&wihf_p, g_wihf);
    cudaGetSymbolAddress((void**)&bias_p, g_bias);
    uint32_t* hf0 = hf_p;
    uint32_t* hf1 = hf_p + 196608;

    const __half* inH[3] = {nullptr, hs0_p, hs1_p};
    __half* outH[3] = {hs0_p, hs1_p, hs0_p};
    int Ks[3] = {NM, HH, HH};
    int Kcs[3] = {3, KC, KC};

    for (int l = 0; l < 3; l++) {
        prepA_kernel<<<(GG * HH + 255) / 256, 256>>>(w_hh[l], (__half*)whhf_p,
                                                     w_ih[l], (__half*)wihf_p,
                                                     Ks[l], Kcs[l]);
        prepB_kernel<<<768, 256>>>(b_ih[l], b_hh[l], bias_p, hf0);
        gemm_in3<<<dim3(GG / 128, (BB * TT) / 128), 256, 49152>>>(
            (l == 0) ? x : nullptr, inH[l], wihf_p, bias_p, xg_p, Ks[l], Kcs[l],
            (l == 0) ? 0 : 1);
        lstm_persist<<<NCTA, 256, LSTM_SMEM>>>(whhf_p, xg_p, hf0, hf1, outH[l],
                                               (l < 2) ? 1 : 0);
    }
    proj_kernel<<<BB / 8, 256>>>(hs0_p, pw, pb, out);
}

// round 16
// speedup vs baseline: 2.0494x; 1.1430x over previous
#include <cuda_runtime.h>
#include <cuda_fp16.h>
#include <cstdint>
#include <math.h>

#define BB 512
#define TT 180
#define NM 40
#define HH 768
#define GG 3072   // 4*HH
#define PR 256
#define KC 48     // HH/16
#define NC64 12   // HH/64
#define NCTA 128  // 8 batch-tiles x 16 j-tiles

// lstm_persist dynamic smem layout (bytes)
#define SXG_OFF 98304      // stages: 3 x 32768
#define GSM_OFF 122880     // sxg: 24576
#define FS_OFF  173056     // gsm: 50176 (64 rows x 196 floats)
#define LSTM_SMEM 179200   // fs: 6144

// ---- static device scratch ----
__device__ __half g_xg[(size_t)TT * BB * GG];        // [t][b][gcol] fp16
__device__ __half g_hseq0[(size_t)BB * TT * HH];
__device__ __half g_hseq1[(size_t)BB * TT * HH];
__device__ uint32_t g_hfrag[2 * 196608];             // A-frag fp16 h (ping-pong)
__device__ uint32_t g_whhf[1179648];                 // B-frag fp16 W_hh: [j0 16][kc 48][ntpair 12][lane 32][4]
__device__ uint32_t g_wihf[1179648];                 // B-frag fp16 W_ih: [n0 24][kc Kc][ntpair 8][lane 32][4]
__device__ float g_bias[GG];
__device__ unsigned g_bar;

__device__ __forceinline__ void mma16(float* d, uint4 a, uint32_t b0, uint32_t b1) {
    asm volatile(
        "mma.sync.aligned.m16n8k16.row.col.f32.f16.f16.f32 "
        "{%0,%1,%2,%3}, {%4,%5,%6,%7}, {%8,%9}, {%0,%1,%2,%3};\n"
        : "+f"(d[0]), "+f"(d[1]), "+f"(d[2]), "+f"(d[3])
        : "r"(a.x), "r"(a.y), "r"(a.z), "r"(a.w), "r"(b0), "r"(b1));
}

__device__ __forceinline__ void cp16(void* s, const void* g) {
    uint32_t sa = (uint32_t)__cvta_generic_to_shared(s);
    asm volatile("cp.async.cg.shared.global [%0], [%1], 16;\n" :: "r"(sa), "l"(g));
}
#define CPCOMMIT() asm volatile("cp.async.commit_group;\n")
#define CPW0() asm volatile("cp.async.wait_group 0;\n")
#define CPW1() asm volatile("cp.async.wait_group 1;\n")

__device__ __forceinline__ float tanh_ap(float x) {
    float y; asm("tanh.approx.f32 %0, %1;" : "=f"(y) : "f"(x)); return y;
}
__device__ __forceinline__ float sig_ap(float x) { return 0.5f * tanh_ap(0.5f * x) + 0.5f; }

__device__ __forceinline__ uint32_t packh2(float lo, float hi) {
    __half2 h = __floats2half2_rn(lo, hi);
    return *(uint32_t*)&h;
}

// ---------------------------------------------------------------------------
// prepA: both weight frag transforms in one launch (layouts unchanged).
// ---------------------------------------------------------------------------
__global__ void prepA_kernel(const float* __restrict__ Whh, __half* __restrict__ whhf,
                             const float* __restrict__ Wih, __half* __restrict__ wihf,
                             int K, int Kc) {
    int idx = blockIdx.x * 256 + threadIdx.x;
    if (idx < GG * HH) {
        int r = idx / HH, k = idx - r * HH;
        int gate = r / HH;
        int jglob = r - gate * HH;
        int j0 = jglob / 48;
        int cj = jglob - j0 * 48;
        int ncol = gate * 48 + cj;
        int kc = k >> 4, kl = k & 15;
        int ntpair = ncol >> 4, sub = (ncol >> 3) & 1, nloc = ncol & 7;
        int lane = nloc * 4 + ((kl & 7) >> 1);
        int reg = kl >> 3;
        size_t u32i = ((((size_t)j0 * KC + kc) * 12 + ntpair) * 32 + lane) * 4 + sub * 2 + reg;
        whhf[u32i * 2 + (kl & 1)] = __float2half(Whh[idx]);
    }
    int kb = Kc * 16;
    if (idx < GG * kb) {
        int r = idx / kb, k = idx - r * kb;
        int n0 = r >> 7, ncol = r & 127;
        int kc = k >> 4, kl = k & 15;
        int ntpair = ncol >> 4, sub = (ncol >> 3) & 1, nloc = ncol & 7;
        int lane = nloc * 4 + ((kl & 7) >> 1);
        int reg = kl >> 3;
        size_t u32i = ((((size_t)n0 * Kc + kc) * 8 + ntpair) * 32 + lane) * 4 + sub * 2 + reg;
        float v = (k < K) ? Wih[(size_t)r * K + k] : 0.f;
        wihf[u32i * 2 + (kl & 1)] = __float2half(v);
    }
}

// ---------------------------------------------------------------------------
__global__ void prepB_kernel(const float* __restrict__ bi, const float* __restrict__ bh,
                             float* __restrict__ bias, uint32_t* __restrict__ hf) {
    int i = blockIdx.x * 256 + threadIdx.x;
    if (i == 0) g_bar = 0u;
    if (i < GG) bias[i] = bi[i] + bh[i];
    if (i < 196608) hf[i] = 0u;
}

// ---------------------------------------------------------------------------
// Input GEMM (unchanged — known good). CTA 128m x 128n, 8 warps.
// ---------------------------------------------------------------------------
__global__ __launch_bounds__(256) void gemm_in3(
    const float* __restrict__ Af, const __half* __restrict__ Ah,
    const uint32_t* __restrict__ Bf, const float* __restrict__ bias,
    __half* __restrict__ out, int K, int Kc, int a_half)
{
    extern __shared__ __align__(16) char smd[];
    uint32_t (*As)[1024] = (uint32_t(*)[1024])smd;
    uint32_t (*Bs)[1024] = (uint32_t(*)[1024])(smd + 8192);
    __half* stg = (__half*)(smd + 16384);

    const int tid = threadIdx.x, lane = tid & 31, wid = tid >> 5;
    const int wm = wid >> 1, wn = wid & 1;
    const int n0 = blockIdx.x, m0 = blockIdx.y;
    const int g = lane >> 2, tg = lane & 3;

    float acc[2][8][4];
    #pragma unroll
    for (int i = 0; i < 2; i++)
        #pragma unroll
        for (int j = 0; j < 8; j++)
            #pragma unroll
            for (int k = 0; k < 4; k++) acc[i][j][k] = 0.f;

    const int row = tid >> 1, kp = (tid & 1) * 8;
    const int mt = row >> 4, mloc = row & 15;
    const int regbase = (kp >> 3) * 2 + (mloc >> 3);
    const uint32_t* Bbase = Bf + (size_t)n0 * Kc * 1024;

    uint32_t av[4];
    auto ldgA = [&](int kc) {
        int k0 = kc * 16;
        if (a_half) {
            const __half* src = Ah + (size_t)(m0 * 128 + row) * K + k0 + kp;
            uint4 v = *(const uint4*)src;
            av[0] = v.x; av[1] = v.y; av[2] = v.z; av[3] = v.w;
        } else {
            float t0[4] = {0, 0, 0, 0}, t1[4] = {0, 0, 0, 0};
            const float* src = Af + (size_t)(m0 * 128 + row) * K + k0 + kp;
            if (k0 + kp < K)     *(float4*)t0 = *(const float4*)src;
            if (k0 + kp + 4 < K) *(float4*)t1 = *(const float4*)(src + 4);
            av[0] = packh2(t0[0], t0[1]); av[1] = packh2(t0[2], t0[3]);
            av[2] = packh2(t1[0], t1[1]); av[3] = packh2(t1[2], t1[3]);
        }
    };
    auto stsA = [&](int buf) {
        #pragma unroll
        for (int i = 0; i < 4; i++)
            As[buf][(mt * 32 + (mloc & 7) * 4 + i) * 4 + regbase] = av[i];
    };
    auto cpB = [&](int buf, int kc) {
        const uint32_t* src = Bbase + (size_t)kc * 1024;
        cp16(&Bs[buf][tid * 4], src + tid * 4);
    };

    ldgA(0); cpB(0, 0); CPCOMMIT();
    stsA(0);
    CPW0();
    __syncthreads();

    for (int kc = 0; kc < Kc; kc++) {
        int cur = kc & 1, nxt = cur ^ 1;
        if (kc + 1 < Kc) { cpB(nxt, kc + 1); CPCOMMIT(); ldgA(kc + 1); }
        uint4 af[2];
        #pragma unroll
        for (int mti = 0; mti < 2; mti++)
            af[mti] = *(const uint4*)&As[cur][((2 * wm + mti) * 32 + lane) * 4];
        #pragma unroll
        for (int p = 0; p < 4; p++) {
            uint4 bq = *(const uint4*)&Bs[cur][((wn * 4 + p) * 32 + lane) * 4];
            mma16(acc[0][2 * p], af[0], bq.x, bq.y);
            mma16(acc[1][2 * p], af[1], bq.x, bq.y);
            mma16(acc[0][2 * p + 1], af[0], bq.z, bq.w);
            mma16(acc[1][2 * p + 1], af[1], bq.z, bq.w);
        }
        if (kc + 1 < Kc) { stsA(nxt); CPW0(); }
        __syncthreads();
    }

    #pragma unroll
    for (int mti = 0; mti < 2; mti++)
        #pragma unroll
        for (int nt = 0; nt < 8; nt++)
            #pragma unroll
            for (int rh = 0; rh < 2; rh++) {
                int rrow = wm * 32 + mti * 16 + g + rh * 8;
                int coll = wn * 64 + nt * 8 + 2 * tg;
                float v0 = acc[mti][nt][rh * 2 + 0] + __ldg(&bias[n0 * 128 + coll]);
                float v1 = acc[mti][nt][rh * 2 + 1] + __ldg(&bias[n0 * 128 + coll + 1]);
                *(__half2*)&stg[rrow * 128 + coll] = __floats2half2_rn(v0, v1);
            }
    __syncthreads();
    #pragma unroll
    for (int i = 0; i < 8; i++) {
        int unit = tid + i * 256;
        int rrow = unit >> 4, u = unit & 15;
        int m = m0 * 128 + rrow;
        int b = m / TT, t = m - b * TT;
        __half* dst = &out[((size_t)t * BB + b) * GG + n0 * 128];
        *(uint4*)((char*)dst + u * 16) = *(const uint4*)((char*)&stg[rrow * 128] + u * 16);
    }
}

// ---------------------------------------------------------------------------
// Persistent LSTM layer — 384 threads (12 warps: wm 2 x wn 6) for 3 warps/SMSP.
// Warp tile 32m x 32n (2 ntpairs). ALL fragment loads remain LDS.128.
// K-chunk 64, 3 stages, single-pass epilogue, pre-barrier W/xg prefetch.
// ---------------------------------------------------------------------------
__global__ __launch_bounds__(384, 1) void lstm_persist(
    const uint32_t* __restrict__ Wf, const __half* __restrict__ xg,
    uint32_t* __restrict__ hfA, uint32_t* __restrict__ hfB,
    __half* __restrict__ hseq, int seq_all)
{
    extern __shared__ __align__(16) char smc[];
    __half* sxg = (__half*)(smc + SXG_OFF);     // [bl 64][gate 4][cj 48]
    float* gsm = (float*)(smc + GSM_OFF);       // [mi 64][gate 4][49]
    __half* fsh = (__half*)(smc + FS_OFF);
    uint32_t* fsu = (uint32_t*)fsh;

    const int tid = threadIdx.x, lane = tid & 31, wid = tid >> 5;
    const int wm = wid / 6, wn = wid % 6;       // wm 0..1, wn 0..5
    const int m0 = blockIdx.x & 7, j0 = blockIdx.x >> 3;   // j0: 0..15
    const int g = lane >> 2, tg = lane & 3;
    const uint32_t* Bb = Wf + (size_t)j0 * (KC * 1536);

    float creg[8];
    #pragma unroll
    for (int i = 0; i < 8; i++) creg[i] = 0.f;

    const int ecj = tid % 48;
    const int er0 = tid / 48;     // 0..7

    // B-part of a chunk64 stage (t-independent): 1536 uint4 = 4 x 384
    auto cpB = [&](int kcc) {
        uint32_t* dst = (uint32_t*)(smc + (kcc % 3) * 32768);
        const uint32_t* b = Bb + (size_t)kcc * 6144;
        #pragma unroll
        for (int i = 0; i < 4; i++)
            cp16(&dst[2048 + (tid + i * 384) * 4], b + (tid + i * 384) * 4);
    };
    // xg tile prefetch for step tt: 1536 uint4 = 4 x 384
    auto cpXG = [&](int tt) {
        #pragma unroll
        for (int i = 0; i < 4; i++) {
            int u = tid + i * 384;
            int bl = u / 24, rem = u - bl * 24;
            int gate = rem / 6, s = rem - gate * 6;
            const __half* src = xg + ((size_t)tt * BB + m0 * 64 + bl) * GG +
                                gate * HH + j0 * 48 + s * 8;
            cp16(&sxg[(bl * 4 + gate) * 48 + s * 8], src);
        }
    };

    // initial P group for t = 0
    cpB(0); cpB(1); cpXG(0); CPCOMMIT();

    for (int t = 0; t < TT; t++) {
        const uint32_t* Ain = ((t & 1) ? hfB : hfA) + (size_t)m0 * (KC * 512);
        uint32_t* Hout = (t & 1) ? hfA : hfB;

        // A-part of a stage: 512 uint4 = 384 + 128
        auto cpA = [&](int kcc) {
            uint32_t* dst = (uint32_t*)(smc + (kcc % 3) * 32768);
            const uint32_t* a = Ain + (size_t)kcc * 2048;
            cp16(&dst[tid * 4], a + tid * 4);
            if (tid < 128)
                cp16(&dst[(tid + 384) * 4], a + (tid + 384) * 4);
        };

        float acc[2][4][4];   // [mti][pp*2+sub][reg]
        #pragma unroll
        for (int i = 0; i < 2; i++)
            #pragma unroll
            for (int j = 0; j < 4; j++)
                #pragma unroll
                for (int k = 0; k < 4; k++) acc[i][j][k] = 0.f;

        // post-barrier: only A loads are cold
        cpA(0); CPCOMMIT();
        cpA(1); CPCOMMIT();

        for (int kcc = 0; kcc < NC64; kcc++) {
            if (kcc < NC64 - 1) CPW1(); else CPW0();
            __syncthreads();
            if (kcc + 2 < NC64) { cpA(kcc + 2); cpB(kcc + 2); CPCOMMIT(); }
            const uint32_t* stgb = (const uint32_t*)(smc + (kcc % 3) * 32768);
            #pragma unroll
            for (int q = 0; q < 4; q++) {
                const uint32_t* sA = stgb + q * 512;
                const uint32_t* sB = stgb + 2048 + q * 1536;
                uint4 af[2];
                #pragma unroll
                for (int mti = 0; mti < 2; mti++)
                    af[mti] = *(const uint4*)&sA[((2 * wm + mti) * 32 + lane) * 4];
                #pragma unroll
                for (int pp = 0; pp < 2; pp++) {
                    uint4 bq = *(const uint4*)&sB[((wn * 2 + pp) * 32 + lane) * 4];
                    mma16(acc[0][2 * pp], af[0], bq.x, bq.y);
                    mma16(acc[1][2 * pp], af[1], bq.x, bq.y);
                    mma16(acc[0][2 * pp + 1], af[0], bq.z, bq.w);
                    mma16(acc[1][2 * pp + 1], af[1], bq.z, bq.w);
                }
            }
        }

        // ---- unified single-pass epilogue ----
        #pragma unroll
        for (int mti = 0; mti < 2; mti++)
            #pragma unroll
            for (int jj = 0; jj < 4; jj++)
                #pragma unroll
                for (int r2 = 0; r2 < 4; r2++) {
                    int mi = wm * 32 + mti * 16 + g + ((r2 & 2) ? 8 : 0);
                    int ncol = (wn * 2 + (jj >> 1)) * 16 + (jj & 1) * 8 + 2 * tg + (r2 & 1);
                    int gate = ncol / 48;
                    int cj = ncol - gate * 48;
                    gsm[mi * 196 + gate * 49 + cj] = acc[mti][jj][r2];
                }
        __syncthreads();
        {
            #pragma unroll
            for (int i = 0; i < 8; i++) {
                int bl = er0 + 8 * i;          // 0..63
                int b = m0 * 64 + bl;
                int j = j0 * 48 + ecj;
                const __half* xh = &sxg[bl * 192 + ecj];
                float pi = gsm[bl * 196 + 0 * 49 + ecj] + __half2float(xh[0]);
                float pf = gsm[bl * 196 + 1 * 49 + ecj] + __half2float(xh[48]);
                float pg = gsm[bl * 196 + 2 * 49 + ecj] + __half2float(xh[96]);
                float po = gsm[bl * 196 + 3 * 49 + ecj] + __half2float(xh[144]);
                float iv = sig_ap(pi), fv = sig_ap(pf), gv = tanh_ap(pg), ov = sig_ap(po);
                float cn = fv * creg[i] + iv * gv;
                creg[i] = cn;
                float hn = ov * tanh_ap(cn);
                if (seq_all || t == TT - 1)
                    hseq[((size_t)b * TT + t) * HH + j] = __float2half(hn);
                int q = ecj >> 4, kl = ecj & 15;
                int mt = bl >> 4, mloc = bl & 15;
                int lf = (mloc & 7) * 4 + ((kl & 7) >> 1);
                int reg = (kl >> 3) * 2 + (mloc >> 3);
                fsh[((((q * 4 + mt) * 32 + lf) * 4) + reg) * 2 + (kl & 1)] =
                    __float2half(hn);
            }
        }
        __syncthreads();
        if (t < TT - 1) {
            // coalesced frag store (1536 u32 = 384 uint4; 1 per thread)
            size_t fb = ((size_t)m0 * KC + (size_t)j0 * 3) * 512;
            *(uint4*)&Hout[fb + tid * 4] = *(const uint4*)&fsu[tid * 4];
            // prefetch next step's W chunks 0,1 + xg while waiting on the barrier
            cpB(0); cpB(1); cpXG(t + 1); CPCOMMIT();
            __threadfence();
            __syncthreads();
            if (tid == 0) {
                atomicAdd(&g_bar, 1u);
                unsigned target = (unsigned)NCTA * (unsigned)(t + 1);
                while (true) {
                    unsigned v;
                    asm volatile("ld.global.acquire.gpu.u32 %0, [%1];"
                                 : "=r"(v) : "l"(&g_bar));
                    if (v >= target) break;
                    __nanosleep(16);
                }
            }
            __syncthreads();
        }
    }
}

// ---------------------------------------------------------------------------
// Projection + L2 normalize from hseq[:, T-1, :]
// ---------------------------------------------------------------------------
__global__ __launch_bounds__(256) void proj_kernel(
    const __half* __restrict__ hseq, const float* __restrict__ pw,
    const float* __restrict__ pb, float* __restrict__ out)
{
    __shared__ float hs[8][HH];
    __shared__ float red[256];
    const int b0 = blockIdx.x * 8;
    const int tid = threadIdx.x;

    for (int i = tid; i < 8 * HH; i += 256) {
        int r = i / HH, k = i % HH;
        hs[r][k] = __half2float(hseq[((size_t)(b0 + r) * TT + (TT - 1)) * HH + k]);
    }
    __syncthreads();

    float s[8];
    float bias = pb[tid];
    #pragma unroll
    for (int r = 0; r < 8; r++) s[r] = bias;
    const float* w = pw + (size_t)tid * HH;
    for (int k = 0; k < HH; k++) {
        float wv = w[k];
        #pragma unroll
        for (int r = 0; r < 8; r++) s[r] += wv * hs[r][k];
    }

    for (int r = 0; r < 8; r++) {
        red[tid] = s[r] * s[r];
        __syncthreads();
        for (int off = 128; off > 0; off >>= 1) {
            if (tid < off) red[tid] += red[tid + off];
            __syncthreads();
        }
        float rn = rsqrtf(red[0]);
        __syncthreads();
        out[(size_t)(b0 + r) * PR + tid] = s[r] * rn;
    }
}

// ---------------------------------------------------------------------------
// host
// ---------------------------------------------------------------------------
extern "C" void kernel_launch(void* const* d_in, const int* in_sizes, int n_in,
                              void* d_out, int out_size)
{
    const float* x = (const float*)d_in[0];
    const float* w_ih[3] = {(const float*)d_in[1], (const float*)d_in[5], (const float*)d_in[9]};
    const float* w_hh[3] = {(const float*)d_in[2], (const float*)d_in[6], (const float*)d_in[10]};
    const float* b_ih[3] = {(const float*)d_in[3], (const float*)d_in[7], (const float*)d_in[11]};
    const float* b_hh[3] = {(const float*)d_in[4], (const float*)d_in[8], (const float*)d_in[12]};
    const float* pw = (const float*)d_in[13];
    const float* pb = (const float*)d_in[14];
    float* out = (float*)d_out;

    cudaFuncSetAttribute(lstm_persist, cudaFuncAttributeMaxDynamicSharedMemorySize, LSTM_SMEM);
    cudaFuncSetAttribute(gemm_in3, cudaFuncAttributeMaxDynamicSharedMemorySize, 49152);

    __half *xg_p, *hs0_p, *hs1_p;
    uint32_t *hf_p, *whhf_p, *wihf_p;
    float *bias_p;
    cudaGetSymbolAddress((void**)&xg_p, g_xg);
    cudaGetSymbolAddress((void**)&hs0_p, g_hseq0);
    cudaGetSymbolAddress((void**)&hs1_p, g_hseq1);
    cudaGetSymbolAddress((void**)&hf_p, g_hfrag);
    cudaGetSymbolAddress((void**)&whhf_p, g_whhf);
    cudaGetSymbolAddress((void**)&wihf_p, g_wihf);
    cudaGetSymbolAddress((void**)&bias_p, g_bias);
    uint32_t* hf0 = hf_p;
    uint32_t* hf1 = hf_p + 196608;

    const __half* inH[3] = {nullptr, hs0_p, hs1_p};
    __half* outH[3] = {hs0_p, hs1_p, hs0_p};
    int Ks[3] = {NM, HH, HH};
    int Kcs[3] = {3, KC, KC};

    for (int l = 0; l < 3; l++) {
        prepA_kernel<<<(GG * HH + 255) / 256, 256>>>(w_hh[l], (__half*)whhf_p,
                                                     w_ih[l], (__half*)wihf_p,
                                                     Ks[l], Kcs[l]);
        prepB_kernel<<<768, 256>>>(b_ih[l], b_hh[l], bias_p, hf0);
        gemm_in3<<<dim3(GG / 128, (BB * TT) / 128), 256, 49152>>>(
            (l == 0) ? x : nullptr, inH[l], wihf_p, bias_p, xg_p, Ks[l], Kcs[l],
            (l == 0) ? 0 : 1);
        lstm_persist<<<NCTA, 384, LSTM_SMEM>>>(whhf_p, xg_p, hf0, hf1, outH[l],
                                               (l < 2) ? 1 : 0);
    }
    proj_kernel<<<BB / 8, 256>>>(hs0_p, pw, pb, out);
}